// round 5
// baseline (speedup 1.0000x reference)
#include <cuda_runtime.h>
#include <math.h>
#include <stdint.h>

// Problem constants (fixed by setup_inputs)
#define N_NODES 32768
#define NB      64
#define LSEQ    512
#define DIM     256
#define HID     512
#define GI3     1536   // 3*HID
#define EDGES   524288

// ---------------- f32x2 packed math (sm_103a) ----------------
#define FMA2(d, a, b, c) \
    asm("fma.rn.f32x2 %0, %1, %2, %3;" : "=l"(d) : "l"(a), "l"(b), "l"(c))

// ---------------- scratch (static device globals; no allocation) ----------------
__device__ float g_h0 [(size_t)N_NODES * DIM];
__device__ float g_t  [(size_t)N_NODES * HID];
__device__ float g_h1 [(size_t)N_NODES * HID];
__device__ float g_h2 [(size_t)N_NODES * HID];
__device__ float g_gi [(size_t)N_NODES * GI3];
__device__ float g_gi2[(size_t)LSEQ * GI3 * NB];   // [t][gatecol][b]
__device__ int   g_deg [N_NODES];
__device__ float g_dinv[N_NODES];
__device__ int   g_off [N_NODES + 1];
__device__ int   g_cursor[N_NODES];
__device__ int   g_csrc[EDGES];
__device__ float g_ccoef[EDGES];
__device__ float g_hbuf[2][NB * HID];
__device__ float g_hsum[NB * HID];
__device__ int   g_bar[4 * 32];   // one counter per graph-group, separate lines

// ---------------- degree / CSR build ----------------
__global__ void k_count(const int* __restrict__ dst, int* __restrict__ deg, int E) {
    int i = blockIdx.x * 256 + threadIdx.x;
    if (i < E) atomicAdd(&deg[dst[i]], 1);
}

__global__ void k_dinv(const int* __restrict__ deg, float* __restrict__ dinv) {
    int i = blockIdx.x * 256 + threadIdx.x;
    if (i < N_NODES) dinv[i] = rsqrtf((float)(deg[i] + 1));  // +1 self loop
}

__global__ void __launch_bounds__(1024) k_scan(const int* __restrict__ deg,
                                               int* __restrict__ off,
                                               int* __restrict__ cursor) {
    __shared__ int ssum[1024];
    int tid = threadIdx.x;
    int base = tid * 32;
    int loc[32];
    int s = 0;
#pragma unroll
    for (int i = 0; i < 32; i++) { loc[i] = s; s += deg[base + i]; }
    ssum[tid] = s;
    __syncthreads();
    for (int ofs = 1; ofs < 1024; ofs <<= 1) {
        int v = (tid >= ofs) ? ssum[tid - ofs] : 0;
        __syncthreads();
        ssum[tid] += v;
        __syncthreads();
    }
    int pre = (tid == 0) ? 0 : ssum[tid - 1];
#pragma unroll
    for (int i = 0; i < 32; i++) { off[base + i] = pre + loc[i]; cursor[base + i] = 0; }
    if (tid == 1023) off[N_NODES] = ssum[1023];
}

__global__ void k_fill(const int* __restrict__ src, const int* __restrict__ dst,
                       const float* __restrict__ dinv, const int* __restrict__ off,
                       int* __restrict__ cursor, int* __restrict__ csrc,
                       float* __restrict__ ccoef, int E) {
    int e = blockIdx.x * 256 + threadIdx.x;
    if (e >= E) return;
    int s = src[e], d = dst[e];
    int p = atomicAdd(&cursor[d], 1);
    int slot = off[d] + p;
    csrc[slot] = s;
    ccoef[slot] = dinv[s] * dinv[d];
}

__global__ void k_embed(const int* __restrict__ x, const float* __restrict__ emb,
                        float* __restrict__ h0) {
    int n = blockIdx.x;
    int d = threadIdx.x;          // 256 threads
    h0[(size_t)n * DIM + d] = emb[(size_t)x[n] * DIM + d];
}

// ---------------- CSR gather: out = relu( sum_in t[src]*coef + t[n]*dinv^2 + bias )
__global__ void __launch_bounds__(256) k_gather(
    const float* __restrict__ t, const int* __restrict__ csrc,
    const float* __restrict__ ccoef, const int* __restrict__ off,
    const float* __restrict__ dinv, const float* __restrict__ bias,
    float* __restrict__ out) {
    int w = threadIdx.x >> 5, lane = threadIdx.x & 31;
    int n = blockIdx.x * 2 + (w >> 2);
    int chunk = w & 3;
    int c4 = chunk * 32 + lane;   // float4 column index 0..127
    float di = dinv[n];
    float sc = di * di;
    float4 v = ((const float4*)(t + (size_t)n * HID))[c4];
    float4 acc = {v.x * sc, v.y * sc, v.z * sc, v.w * sc};
    int j0 = off[n], j1 = off[n + 1];
#pragma unroll 2
    for (int j = j0; j < j1; j++) {
        int s = __ldg(&csrc[j]);
        float cf = __ldg(&ccoef[j]);
        float4 u = ((const float4*)(t + (size_t)s * HID))[c4];
        acc.x += u.x * cf; acc.y += u.y * cf; acc.z += u.z * cf; acc.w += u.w * cf;
    }
    float4 bb = ((const float4*)bias)[c4];
    float4 o = {fmaxf(acc.x + bb.x, 0.f), fmaxf(acc.y + bb.y, 0.f),
                fmaxf(acc.z + bb.z, 0.f), fmaxf(acc.w + bb.w, 0.f)};
    ((float4*)(out + (size_t)n * HID))[c4] = o;
}

// ---------------- tiled SGEMM: C[M,N] = A[M,K] @ (B or B^T) (+bias) ----------------
template<bool TRANSB, bool ADD_BIAS>
__global__ void __launch_bounds__(256) sgemm_kernel(
    const float* __restrict__ A, const float* __restrict__ B,
    const float* __restrict__ bias, float* __restrict__ C,
    int M, int N, int K) {
    __shared__ float As[16][64];
    __shared__ float Bs[16][64];
    int tid = threadIdx.x;
    int tx = tid & 15, ty = tid >> 4;
    int row0 = blockIdx.y * 64;
    int col0 = blockIdx.x * 64;
    float acc[4][4] = {};
    int la_m = tid >> 2;
    int la_k = (tid & 3) << 2;
    for (int kk = 0; kk < K; kk += 16) {
        {
            float4 v = *(const float4*)(A + (size_t)(row0 + la_m) * K + kk + la_k);
            As[la_k + 0][la_m] = v.x; As[la_k + 1][la_m] = v.y;
            As[la_k + 2][la_m] = v.z; As[la_k + 3][la_m] = v.w;
        }
        if (TRANSB) {
            float4 v = *(const float4*)(B + (size_t)(col0 + la_m) * K + kk + la_k);
            Bs[la_k + 0][la_m] = v.x; Bs[la_k + 1][la_m] = v.y;
            Bs[la_k + 2][la_m] = v.z; Bs[la_k + 3][la_m] = v.w;
        } else {
            int lb_k = tid >> 4;
            int lb_n = (tid & 15) << 2;
            float4 v = *(const float4*)(B + (size_t)(kk + lb_k) * N + col0 + lb_n);
            *(float4*)&Bs[lb_k][lb_n] = v;
        }
        __syncthreads();
#pragma unroll
        for (int k = 0; k < 16; k++) {
            float4 a  = *(const float4*)&As[k][ty << 2];
            float4 bv = *(const float4*)&Bs[k][tx << 2];
            acc[0][0] += a.x * bv.x; acc[0][1] += a.x * bv.y; acc[0][2] += a.x * bv.z; acc[0][3] += a.x * bv.w;
            acc[1][0] += a.y * bv.x; acc[1][1] += a.y * bv.y; acc[1][2] += a.y * bv.z; acc[1][3] += a.y * bv.w;
            acc[2][0] += a.z * bv.x; acc[2][1] += a.z * bv.y; acc[2][2] += a.z * bv.z; acc[2][3] += a.z * bv.w;
            acc[3][0] += a.w * bv.x; acc[3][1] += a.w * bv.y; acc[3][2] += a.w * bv.z; acc[3][3] += a.w * bv.w;
        }
        __syncthreads();
    }
    float4 bb = {0, 0, 0, 0};
    if (ADD_BIAS) bb = *(const float4*)(bias + col0 + (tx << 2));
#pragma unroll
    for (int i = 0; i < 4; i++) {
        float4 o = {acc[i][0] + bb.x, acc[i][1] + bb.y, acc[i][2] + bb.z, acc[i][3] + bb.w};
        *(float4*)(C + (size_t)(row0 + (ty << 2) + i) * N + col0 + (tx << 2)) = o;
    }
}

// ---------------- gi transpose: gi[b*512+t][j] -> gi2[t][j][b] ----------------
__global__ void __launch_bounds__(256) k_tr(const float* __restrict__ gi,
                                            float* __restrict__ gi2) {
    __shared__ float s[64][132];
    int tid = threadIdx.x;
    int t = blockIdx.x;
    int j0 = blockIdx.y * 128;
#pragma unroll
    for (int i = 0; i < 8; i++) {
        int idx = tid + i * 256;
        int b = idx >> 5, c4 = idx & 31;
        float4 v = ((const float4*)(gi + (size_t)(b * LSEQ + t) * GI3 + j0))[c4];
        *(float4*)&s[b][c4 * 4] = v;
    }
    __syncthreads();
    size_t obase = (size_t)t * (GI3 * NB);
#pragma unroll
    for (int i = 0; i < 32; i++) {
        int idx = tid + i * 256;
        int j = idx >> 6, b = idx & 63;
        gi2[obase + (size_t)(j0 + j) * NB + b] = s[b][j];
    }
}

// ---------------- persistent GRU, graph-partitioned ----------------
// 128 blocks = 4 graph-groups x 32 col-groups. Block owns 16 graphs x 16 cols.
// Thread = (c 0..15, g 0..15) computes the 3 gate dots over full K=512 with
// f32x2 (no cross-thread reduction). Per-step exchange only within the 32
// blocks of a graph-group (32 KB staged, 32-wide barrier).
// Warp layout: 4 cols x 8 graphs -> per k4: 1 h-wavefront + 3 w-wavefronts.
#define HS_ROWS 16
#define WS_ROWS 48        // 16 cols x 3 gates, row = c*3+gate
#define ROW_F4  129       // float4 stride (odd -> conflict-free)
#define GRU_SMEM ((HS_ROWS + WS_ROWS) * ROW_F4 * 16)   // 132096 B

__device__ __forceinline__ float sigmoidf_(float x) { return 1.0f / (1.0f + __expf(-x)); }

__global__ void __launch_bounds__(256, 1) k_gru_all(
    const float* __restrict__ gi2, const float* __restrict__ Whh,
    const float* __restrict__ bhh, float* __restrict__ hsum,
    float* __restrict__ hbuf0, float* __restrict__ hbuf1, int* bar) {
    extern __shared__ float4 sm4[];
    float4* hs = sm4;                       // [16][ROW_F4]
    float4* ws = sm4 + HS_ROWS * ROW_F4;    // [48][ROW_F4]
    int tid = threadIdx.x;
    int bk = blockIdx.x;
    int grp = bk >> 5;            // graph group 0..3
    int cg  = bk & 31;            // col group 0..31
    int col0 = cg * 16;
    int g0 = grp * 16;
    volatile int* vbar = (volatile int*)(bar + grp * 32);

    // load Whh slab once: ws[c*3+gate][k4] = Whh[gate*HID + col0 + c][k4]
#pragma unroll
    for (int i = 0; i < 24; i++) {
        int idx = tid + i * 256;           // 0..6143
        int r = idx >> 7, k4 = idx & 127;  // r 0..47
        int c = r / 3, gate = r - c * 3;
        ws[r * ROW_F4 + k4] =
            __ldg((const float4*)Whh + (size_t)(gate * HID + col0 + c) * 128 + k4);
    }

    // thread identity: warp = 4 cols x 8 graphs
    int lane = tid & 31, w = tid >> 5;
    int c = (w & 3) * 4 + (lane >> 3);     // 0..15
    int g = (lane & 7) + ((w >> 2) * 8);   // 0..15
    int col = col0 + c;
    int gg  = g0 + g;
    float bh_r = bhh[col], bh_z = bhh[HID + col], bh_n = bhh[2 * HID + col];
    const ulonglong2* hrow = (const ulonglong2*)(hs + g * ROW_F4);
    const ulonglong2* wrp  = (const ulonglong2*)(ws + (c * 3 + 0) * ROW_F4);
    const ulonglong2* wzp  = (const ulonglong2*)(ws + (c * 3 + 1) * ROW_F4);
    const ulonglong2* wnp  = (const ulonglong2*)(ws + (c * 3 + 2) * ROW_F4);
    float hsum_acc = 0.0f;
    __syncthreads();

    for (int t = 0; t < LSEQ; t++) {
        const float* hb = (t & 1) ? hbuf1 : hbuf0;
        float*       hn = (t & 1) ? hbuf0 : hbuf1;

        // prefetch gate inputs for this step
        size_t gbase = (size_t)t * (GI3 * NB) + (size_t)col * NB + gg;
        float gir = __ldcg(gi2 + gbase);
        float giz = __ldcg(gi2 + gbase + (size_t)HID * NB);
        float gin = __ldcg(gi2 + gbase + (size_t)(2 * HID) * NB);

        // stage this group's 16 graphs of h (32 KB), bypass L1
        const float4* hb4 = (const float4*)(hb + (size_t)g0 * HID);
#pragma unroll
        for (int i = 0; i < 8; i++) {
            int idx = tid + i * 256;            // 0..2047
            hs[(idx >> 7) * ROW_F4 + (idx & 127)] = __ldcg(hb4 + idx);
        }
        __syncthreads();

        // 3 full-K dots with pairwise f32x2 (lane0=k-even, lane1=k-odd)
        unsigned long long ar = 0, ar2 = 0, az = 0, az2 = 0, an = 0, an2 = 0;
#pragma unroll 8
        for (int k4 = 0; k4 < 128; k4++) {
            ulonglong2 hv = hrow[k4];
            ulonglong2 wr = wrp[k4], wz = wzp[k4], wn = wnp[k4];
            FMA2(ar, hv.x, wr.x, ar);  FMA2(ar2, hv.y, wr.y, ar2);
            FMA2(az, hv.x, wz.x, az);  FMA2(az2, hv.y, wz.y, az2);
            FMA2(an, hv.x, wn.x, an);  FMA2(an2, hv.y, wn.y, an2);
        }
        float2 f0 = *(float2*)&ar,  f1 = *(float2*)&ar2;
        float sr = (f0.x + f0.y) + (f1.x + f1.y);
        f0 = *(float2*)&az;  f1 = *(float2*)&az2;
        float sz = (f0.x + f0.y) + (f1.x + f1.y);
        f0 = *(float2*)&an;  f1 = *(float2*)&an2;
        float sn = (f0.x + f0.y) + (f1.x + f1.y);

        float r  = sigmoidf_(gir + sr + bh_r);
        float z  = sigmoidf_(giz + sz + bh_z);
        float nn = tanhf(gin + r * (sn + bh_n));
        float hold = ((const float*)(hs + g * ROW_F4))[col];
        float hnew = (1.0f - z) * nn + z * hold;
        __stcg(hn + (size_t)gg * HID + col, hnew);
        hsum_acc += hnew;

        // group-wide barrier (32 blocks sharing this graph group)
        __threadfence();
        __syncthreads();
        if (tid == 0) {
            atomicAdd((int*)vbar, 1);
            int target = 32 * (t + 1);
            while (*vbar < target) { }
        }
        __syncthreads();
    }
    hsum[(size_t)gg * HID + col] = hsum_acc;
}

// ---------------- head ----------------
__global__ void __launch_bounds__(512) k_head(
    const float* __restrict__ hsum, const float* __restrict__ focal,
    const float* __restrict__ fc1w, const float* __restrict__ fc1b,
    const float* __restrict__ fc2w, const float* __restrict__ fc2b,
    float* __restrict__ out) {
    __shared__ float g[HID + 1];
    __shared__ float red[HID];
    int b = blockIdx.x, j = threadIdx.x;
    g[j] = hsum[b * HID + j] * (1.0f / (float)LSEQ);
    if (j == 0) g[HID] = focal[b];
    __syncthreads();
    float acc = fc1b[j];
    for (int k = 0; k < HID + 1; k++) acc += g[k] * fc1w[(size_t)k * HID + j];
    float a = fmaxf(acc, 0.0f);
    red[j] = a * fc2w[j];
    __syncthreads();
    for (int s = 256; s > 0; s >>= 1) {
        if (j < s) red[j] += red[j + s];
        __syncthreads();
    }
    if (j == 0) out[b] = sigmoidf_(red[0] + fc2b[0]);
}

// ---------------- launch ----------------
extern "C" void kernel_launch(void* const* d_in, const int* in_sizes, int n_in,
                              void* d_out, int out_size) {
    const int*   x     = (const int*)  d_in[0];
    const int*   edge  = (const int*)  d_in[1];
    const float* focal = (const float*)d_in[3];
    const float* emb   = (const float*)d_in[4];
    const float* W1    = (const float*)d_in[5];
    const float* b1    = (const float*)d_in[6];
    const float* W2    = (const float*)d_in[7];
    const float* b2    = (const float*)d_in[8];
    const float* Wih   = (const float*)d_in[9];
    const float* Whh   = (const float*)d_in[10];
    const float* bih   = (const float*)d_in[11];
    const float* bhh   = (const float*)d_in[12];
    const float* fc1w  = (const float*)d_in[13];
    const float* fc1b  = (const float*)d_in[14];
    const float* fc2w  = (const float*)d_in[15];
    const float* fc2b  = (const float*)d_in[16];
    int E = in_sizes[1] / 2;
    const int* src = edge;
    const int* dst = edge + E;

    float *h0, *t, *h1, *h2, *gi, *gi2, *dinv, *hbuf, *hsum, *ccoef;
    int *deg, *off, *cursor, *csrc, *bar;
    cudaGetSymbolAddress((void**)&h0,    g_h0);
    cudaGetSymbolAddress((void**)&t,     g_t);
    cudaGetSymbolAddress((void**)&h1,    g_h1);
    cudaGetSymbolAddress((void**)&h2,    g_h2);
    cudaGetSymbolAddress((void**)&gi,    g_gi);
    cudaGetSymbolAddress((void**)&gi2,   g_gi2);
    cudaGetSymbolAddress((void**)&deg,   g_deg);
    cudaGetSymbolAddress((void**)&dinv,  g_dinv);
    cudaGetSymbolAddress((void**)&off,   g_off);
    cudaGetSymbolAddress((void**)&cursor,g_cursor);
    cudaGetSymbolAddress((void**)&csrc,  g_csrc);
    cudaGetSymbolAddress((void**)&ccoef, g_ccoef);
    cudaGetSymbolAddress((void**)&hbuf,  g_hbuf);
    cudaGetSymbolAddress((void**)&hsum,  g_hsum);
    cudaGetSymbolAddress((void**)&bar,   g_bar);

    cudaFuncSetAttribute(k_gru_all, cudaFuncAttributeMaxDynamicSharedMemorySize, GRU_SMEM);

    // CSR build (graph fixed for both layers)
    cudaMemsetAsync(deg, 0, N_NODES * sizeof(int), 0);
    k_count<<<(E + 255) / 256, 256>>>(dst, deg, E);
    k_dinv<<<N_NODES / 256, 256>>>(deg, dinv);
    k_scan<<<1, 1024>>>(deg, off, cursor);
    k_fill<<<(E + 255) / 256, 256>>>(src, dst, dinv, off, cursor, csrc, ccoef, E);

    // GCN layer 1
    k_embed<<<N_NODES, 256>>>(x, emb, h0);
    sgemm_kernel<false, false><<<dim3(HID / 64, N_NODES / 64), 256>>>(h0, W1, nullptr, t, N_NODES, HID, DIM);
    k_gather<<<N_NODES / 2, 256>>>(t, csrc, ccoef, off, dinv, b1, h1);

    // GCN layer 2
    sgemm_kernel<false, false><<<dim3(HID / 64, N_NODES / 64), 256>>>(h1, W2, nullptr, t, N_NODES, HID, HID);
    k_gather<<<N_NODES / 2, 256>>>(t, csrc, ccoef, off, dinv, b2, h2);

    // GRU input gates for all timesteps: gi = h2 @ Wih^T + bih, then transpose
    sgemm_kernel<true, true><<<dim3(GI3 / 64, N_NODES / 64), 256>>>(h2, Wih, bih, gi, N_NODES, GI3, HID);
    k_tr<<<dim3(LSEQ, GI3 / 128), 256>>>(gi, gi2);

    // persistent GRU
    cudaMemsetAsync(hbuf, 0, NB * HID * sizeof(float), 0);   // hbuf[0] = h_0 = 0
    cudaMemsetAsync(bar, 0, 4 * 32 * sizeof(int), 0);
    k_gru_all<<<128, 256, GRU_SMEM>>>(gi2, Whh, bhh, hsum, hbuf, hbuf + NB * HID, bar);

    // head
    k_head<<<NB, 512>>>(hsum, focal, fc1w, fc1b, fc2w, fc2b, (float*)d_out);
}

// round 6
// speedup vs baseline: 1.1655x; 1.1655x over previous
#include <cuda_runtime.h>
#include <math.h>
#include <stdint.h>

// Problem constants (fixed by setup_inputs)
#define N_NODES 32768
#define NB      64
#define LSEQ    512
#define DIM     256
#define HID     512
#define GI3     1536   // 3*HID
#define EDGES   524288

// ---------------- f32x2 packed math (sm_103a) ----------------
#define FMA2(d, a, b, c) \
    asm("fma.rn.f32x2 %0, %1, %2, %3;" : "=l"(d) : "l"(a), "l"(b), "l"(c))

// ---------------- scratch (static device globals; no allocation) ----------------
__device__ float g_h0 [(size_t)N_NODES * DIM];
__device__ float g_t  [(size_t)N_NODES * HID];
__device__ float g_h1 [(size_t)N_NODES * HID];
__device__ float g_h2 [(size_t)N_NODES * HID];
__device__ float g_gi [(size_t)N_NODES * GI3];
__device__ float g_gi2[(size_t)LSEQ * GI3 * NB];   // [t][gatecol][b]
__device__ int   g_deg [N_NODES];
__device__ float g_dinv[N_NODES];
__device__ int   g_off [N_NODES + 1];
__device__ int   g_cursor[N_NODES];
__device__ int   g_csrc[EDGES];
__device__ float g_ccoef[EDGES];
__device__ float g_hbuf[2][NB * HID];
__device__ float g_hsum[NB * HID];
__device__ int   g_bar[4 * 32];   // one counter per graph-group, separate lines

// ---------------- degree / CSR build ----------------
__global__ void k_count(const int* __restrict__ dst, int* __restrict__ deg, int E) {
    int i = blockIdx.x * 256 + threadIdx.x;
    if (i < E) atomicAdd(&deg[dst[i]], 1);
}

__global__ void k_dinv(const int* __restrict__ deg, float* __restrict__ dinv) {
    int i = blockIdx.x * 256 + threadIdx.x;
    if (i < N_NODES) dinv[i] = rsqrtf((float)(deg[i] + 1));  // +1 self loop
}

__global__ void __launch_bounds__(1024) k_scan(const int* __restrict__ deg,
                                               int* __restrict__ off,
                                               int* __restrict__ cursor) {
    __shared__ int ssum[1024];
    int tid = threadIdx.x;
    int base = tid * 32;
    int loc[32];
    int s = 0;
#pragma unroll
    for (int i = 0; i < 32; i++) { loc[i] = s; s += deg[base + i]; }
    ssum[tid] = s;
    __syncthreads();
    for (int ofs = 1; ofs < 1024; ofs <<= 1) {
        int v = (tid >= ofs) ? ssum[tid - ofs] : 0;
        __syncthreads();
        ssum[tid] += v;
        __syncthreads();
    }
    int pre = (tid == 0) ? 0 : ssum[tid - 1];
#pragma unroll
    for (int i = 0; i < 32; i++) { off[base + i] = pre + loc[i]; cursor[base + i] = 0; }
    if (tid == 1023) off[N_NODES] = ssum[1023];
}

__global__ void k_fill(const int* __restrict__ src, const int* __restrict__ dst,
                       const float* __restrict__ dinv, const int* __restrict__ off,
                       int* __restrict__ cursor, int* __restrict__ csrc,
                       float* __restrict__ ccoef, int E) {
    int e = blockIdx.x * 256 + threadIdx.x;
    if (e >= E) return;
    int s = src[e], d = dst[e];
    int p = atomicAdd(&cursor[d], 1);
    int slot = off[d] + p;
    csrc[slot] = s;
    ccoef[slot] = dinv[s] * dinv[d];
}

__global__ void k_embed(const int* __restrict__ x, const float* __restrict__ emb,
                        float* __restrict__ h0) {
    int n = blockIdx.x;
    int d = threadIdx.x;          // 256 threads
    h0[(size_t)n * DIM + d] = emb[(size_t)x[n] * DIM + d];
}

// ---------------- CSR gather: out = relu( sum_in t[src]*coef + t[n]*dinv^2 + bias )
__global__ void __launch_bounds__(256) k_gather(
    const float* __restrict__ t, const int* __restrict__ csrc,
    const float* __restrict__ ccoef, const int* __restrict__ off,
    const float* __restrict__ dinv, const float* __restrict__ bias,
    float* __restrict__ out) {
    int w = threadIdx.x >> 5, lane = threadIdx.x & 31;
    int n = blockIdx.x * 2 + (w >> 2);
    int chunk = w & 3;
    int c4 = chunk * 32 + lane;   // float4 column index 0..127
    float di = dinv[n];
    float sc = di * di;
    float4 v = ((const float4*)(t + (size_t)n * HID))[c4];
    float4 acc = {v.x * sc, v.y * sc, v.z * sc, v.w * sc};
    int j0 = off[n], j1 = off[n + 1];
#pragma unroll 2
    for (int j = j0; j < j1; j++) {
        int s = __ldg(&csrc[j]);
        float cf = __ldg(&ccoef[j]);
        float4 u = ((const float4*)(t + (size_t)s * HID))[c4];
        acc.x += u.x * cf; acc.y += u.y * cf; acc.z += u.z * cf; acc.w += u.w * cf;
    }
    float4 bb = ((const float4*)bias)[c4];
    float4 o = {fmaxf(acc.x + bb.x, 0.f), fmaxf(acc.y + bb.y, 0.f),
                fmaxf(acc.z + bb.z, 0.f), fmaxf(acc.w + bb.w, 0.f)};
    ((float4*)(out + (size_t)n * HID))[c4] = o;
}

// ---------------- tiled SGEMM: C[M,N] = A[M,K] @ (B or B^T) (+bias) ----------------
template<bool TRANSB, bool ADD_BIAS>
__global__ void __launch_bounds__(256) sgemm_kernel(
    const float* __restrict__ A, const float* __restrict__ B,
    const float* __restrict__ bias, float* __restrict__ C,
    int M, int N, int K) {
    __shared__ float As[16][64];
    __shared__ float Bs[16][64];
    int tid = threadIdx.x;
    int tx = tid & 15, ty = tid >> 4;
    int row0 = blockIdx.y * 64;
    int col0 = blockIdx.x * 64;
    float acc[4][4] = {};
    int la_m = tid >> 2;
    int la_k = (tid & 3) << 2;
    for (int kk = 0; kk < K; kk += 16) {
        {
            float4 v = *(const float4*)(A + (size_t)(row0 + la_m) * K + kk + la_k);
            As[la_k + 0][la_m] = v.x; As[la_k + 1][la_m] = v.y;
            As[la_k + 2][la_m] = v.z; As[la_k + 3][la_m] = v.w;
        }
        if (TRANSB) {
            float4 v = *(const float4*)(B + (size_t)(col0 + la_m) * K + kk + la_k);
            Bs[la_k + 0][la_m] = v.x; Bs[la_k + 1][la_m] = v.y;
            Bs[la_k + 2][la_m] = v.z; Bs[la_k + 3][la_m] = v.w;
        } else {
            int lb_k = tid >> 4;
            int lb_n = (tid & 15) << 2;
            float4 v = *(const float4*)(B + (size_t)(kk + lb_k) * N + col0 + lb_n);
            *(float4*)&Bs[lb_k][lb_n] = v;
        }
        __syncthreads();
#pragma unroll
        for (int k = 0; k < 16; k++) {
            float4 a  = *(const float4*)&As[k][ty << 2];
            float4 bv = *(const float4*)&Bs[k][tx << 2];
            acc[0][0] += a.x * bv.x; acc[0][1] += a.x * bv.y; acc[0][2] += a.x * bv.z; acc[0][3] += a.x * bv.w;
            acc[1][0] += a.y * bv.x; acc[1][1] += a.y * bv.y; acc[1][2] += a.y * bv.z; acc[1][3] += a.y * bv.w;
            acc[2][0] += a.z * bv.x; acc[2][1] += a.z * bv.y; acc[2][2] += a.z * bv.z; acc[2][3] += a.z * bv.w;
            acc[3][0] += a.w * bv.x; acc[3][1] += a.w * bv.y; acc[3][2] += a.w * bv.z; acc[3][3] += a.w * bv.w;
        }
        __syncthreads();
    }
    float4 bb = {0, 0, 0, 0};
    if (ADD_BIAS) bb = *(const float4*)(bias + col0 + (tx << 2));
#pragma unroll
    for (int i = 0; i < 4; i++) {
        float4 o = {acc[i][0] + bb.x, acc[i][1] + bb.y, acc[i][2] + bb.z, acc[i][3] + bb.w};
        *(float4*)(C + (size_t)(row0 + (ty << 2) + i) * N + col0 + (tx << 2)) = o;
    }
}

// ---------------- gi transpose: gi[b*512+t][j] -> gi2[t][j][b] ----------------
__global__ void __launch_bounds__(256) k_tr(const float* __restrict__ gi,
                                            float* __restrict__ gi2) {
    __shared__ float s[64][132];
    int tid = threadIdx.x;
    int t = blockIdx.x;
    int j0 = blockIdx.y * 128;
#pragma unroll
    for (int i = 0; i < 8; i++) {
        int idx = tid + i * 256;
        int b = idx >> 5, c4 = idx & 31;
        float4 v = ((const float4*)(gi + (size_t)(b * LSEQ + t) * GI3 + j0))[c4];
        *(float4*)&s[b][c4 * 4] = v;
    }
    __syncthreads();
    size_t obase = (size_t)t * (GI3 * NB);
#pragma unroll
    for (int i = 0; i < 32; i++) {
        int idx = tid + i * 256;
        int j = idx >> 6, b = idx & 63;
        gi2[obase + (size_t)(j0 + j) * NB + b] = s[b][j];
    }
}

// ---------------- persistent GRU: graph-partitioned + register-tiled ----------------
// 128 blocks = 4 graph-groups x 32 col-groups; block = 16 graphs x 16 cols.
// 256 threads = 4 k-groups x 64 workers; worker (c 0..15, gq 0..3) computes
// 4 graphs {gq, gq+4, gq+8, gq+12} x 1 col x 3 gates over K/4=128.
// Per k4: 7 LDS.128 -> 24 FMA2 (R4's intensity). Then 4-way k reduction in smem.
#define GROW    129                     // float4 stride per smem row
#define REDS    13                      // floats per reduction slot row
#define GRU_SMEM ((16 + 48) * GROW * 16 + 4 * 64 * REDS * 4)   // 145408 B

__device__ __forceinline__ float sigmoidf_(float x) { return 1.0f / (1.0f + __expf(-x)); }

__global__ void __launch_bounds__(256, 1) k_gru_all(
    const float* __restrict__ gi2, const float* __restrict__ Whh,
    const float* __restrict__ bhh, float* __restrict__ hsum,
    float* __restrict__ hbuf0, float* __restrict__ hbuf1, int* bar) {
    extern __shared__ float4 sm4[];
    float4* hs = sm4;                    // [16][GROW]
    float4* ws = sm4 + 16 * GROW;        // [48][GROW]  row = c*3+gate
    float*  red = (float*)(sm4 + 64 * GROW);   // [4*64][REDS]
    int tid = threadIdx.x;
    int bk = blockIdx.x;
    int grp = bk >> 5;                   // graph group 0..3
    int cg  = bk & 31;                   // col group 0..31
    int col0 = cg * 16;
    int g0 = grp * 16;
    volatile int* vbar = (volatile int*)(bar + grp * 32);

    // load Whh slab once: ws[c*3+gate][k4] = Whh[gate*HID + col0 + c][k4]
#pragma unroll
    for (int i = 0; i < 24; i++) {
        int idx = tid + i * 256;           // 0..6143
        int r = idx >> 7, k4 = idx & 127;  // r 0..47
        int c = r / 3, gate = r - c * 3;
        ws[r * GROW + k4] =
            __ldg((const float4*)Whh + (size_t)(gate * HID + col0 + c) * 128 + k4);
    }

    // compute-phase identity
    int kg = tid >> 6;                  // k-group 0..3
    int worker = tid & 63;
    int wc = worker >> 2;               // col 0..15
    int gq = worker & 3;                // graph-quad: graphs gq+4i
    int kbase = kg * 32;
    const ulonglong2* hp0 = (const ulonglong2*)(hs + (gq +  0) * GROW);
    const ulonglong2* hp1 = (const ulonglong2*)(hs + (gq +  4) * GROW);
    const ulonglong2* hp2 = (const ulonglong2*)(hs + (gq +  8) * GROW);
    const ulonglong2* hp3 = (const ulonglong2*)(hs + (gq + 12) * GROW);
    const ulonglong2* wrp = (const ulonglong2*)(ws + (wc * 3 + 0) * GROW);
    const ulonglong2* wzp = (const ulonglong2*)(ws + (wc * 3 + 1) * GROW);
    const ulonglong2* wnp = (const ulonglong2*)(ws + (wc * 3 + 2) * GROW);
    float* myred = red + (kg * 64 + worker) * REDS;

    // gate-phase identity
    int c2 = tid >> 4, g2 = tid & 15;
    int col = col0 + c2;
    int gg  = g0 + g2;
    int worker2 = c2 * 4 + (g2 & 3);    // worker holding (g2, c2)
    int ii = g2 >> 2;                   // register index within that worker
    float bh_r = bhh[col], bh_z = bhh[HID + col], bh_n = bhh[2 * HID + col];
    float hsum_acc = 0.0f;
    __syncthreads();

    for (int t = 0; t < LSEQ; t++) {
        const float* hb = (t & 1) ? hbuf1 : hbuf0;
        float*       hn = (t & 1) ? hbuf0 : hbuf1;

        // prefetch gate inputs for this step
        size_t gbase = (size_t)t * (GI3 * NB) + (size_t)col * NB + gg;
        float gir = __ldcg(gi2 + gbase);
        float giz = __ldcg(gi2 + gbase + (size_t)HID * NB);
        float gin = __ldcg(gi2 + gbase + (size_t)(2 * HID) * NB);

        // stage this group's 16 graphs of h (32 KB), bypass L1
        const float4* hb4 = (const float4*)(hb + (size_t)g0 * HID);
#pragma unroll
        for (int i = 0; i < 8; i++) {
            int idx = tid + i * 256;            // 0..2047
            hs[(idx >> 7) * GROW + (idx & 127)] = __ldcg(hb4 + idx);
        }
        __syncthreads();

        float hold = ((const float*)(hs + g2 * GROW))[col];

        // 12 partial dots over this k-group (pairwise f32x2)
        unsigned long long a0[4], a1[4], a2[4];
#pragma unroll
        for (int i = 0; i < 4; i++) { a0[i] = 0ull; a1[i] = 0ull; a2[i] = 0ull; }
#pragma unroll 8
        for (int kk = 0; kk < 32; kk++) {
            int k4 = kbase + kk;
            ulonglong2 h0 = hp0[k4], h1 = hp1[k4], h2 = hp2[k4], h3 = hp3[k4];
            ulonglong2 wr = wrp[k4], wz = wzp[k4], wn = wnp[k4];
            FMA2(a0[0], h0.x, wr.x, a0[0]); FMA2(a0[0], h0.y, wr.y, a0[0]);
            FMA2(a0[1], h1.x, wr.x, a0[1]); FMA2(a0[1], h1.y, wr.y, a0[1]);
            FMA2(a0[2], h2.x, wr.x, a0[2]); FMA2(a0[2], h2.y, wr.y, a0[2]);
            FMA2(a0[3], h3.x, wr.x, a0[3]); FMA2(a0[3], h3.y, wr.y, a0[3]);
            FMA2(a1[0], h0.x, wz.x, a1[0]); FMA2(a1[0], h0.y, wz.y, a1[0]);
            FMA2(a1[1], h1.x, wz.x, a1[1]); FMA2(a1[1], h1.y, wz.y, a1[1]);
            FMA2(a1[2], h2.x, wz.x, a1[2]); FMA2(a1[2], h2.y, wz.y, a1[2]);
            FMA2(a1[3], h3.x, wz.x, a1[3]); FMA2(a1[3], h3.y, wz.y, a1[3]);
            FMA2(a2[0], h0.x, wn.x, a2[0]); FMA2(a2[0], h0.y, wn.y, a2[0]);
            FMA2(a2[1], h1.x, wn.x, a2[1]); FMA2(a2[1], h1.y, wn.y, a2[1]);
            FMA2(a2[2], h2.x, wn.x, a2[2]); FMA2(a2[2], h2.y, wn.y, a2[2]);
            FMA2(a2[3], h3.x, wn.x, a2[3]); FMA2(a2[3], h3.y, wn.y, a2[3]);
        }
#pragma unroll
        for (int i = 0; i < 4; i++) {
            float2 f;
            f = *(float2*)&a0[i]; myred[0 + i] = f.x + f.y;
            f = *(float2*)&a1[i]; myred[4 + i] = f.x + f.y;
            f = *(float2*)&a2[i]; myred[8 + i] = f.x + f.y;
        }
        __syncthreads();

        // reduce across 4 k-groups + gates + state update
        float s0 = 0, s1 = 0, s2 = 0;
#pragma unroll
        for (int q = 0; q < 4; q++) {
            const float* rp = red + (q * 64 + worker2) * REDS + ii;
            s0 += rp[0]; s1 += rp[4]; s2 += rp[8];
        }
        float r  = sigmoidf_(gir + s0 + bh_r);
        float z  = sigmoidf_(giz + s1 + bh_z);
        float nn = tanhf(gin + r * (s2 + bh_n));
        float hnew = (1.0f - z) * nn + z * hold;
        __stcg(hn + (size_t)gg * HID + col, hnew);
        hsum_acc += hnew;

        // group-wide barrier (32 blocks sharing this graph group)
        __threadfence();
        __syncthreads();
        if (tid == 0) {
            atomicAdd((int*)vbar, 1);
            int target = 32 * (t + 1);
            while (*vbar < target) { }
        }
        __syncthreads();
    }
    hsum[(size_t)gg * HID + col] = hsum_acc;
}

// ---------------- head ----------------
__global__ void __launch_bounds__(512) k_head(
    const float* __restrict__ hsum, const float* __restrict__ focal,
    const float* __restrict__ fc1w, const float* __restrict__ fc1b,
    const float* __restrict__ fc2w, const float* __restrict__ fc2b,
    float* __restrict__ out) {
    __shared__ float g[HID + 1];
    __shared__ float red[HID];
    int b = blockIdx.x, j = threadIdx.x;
    g[j] = hsum[b * HID + j] * (1.0f / (float)LSEQ);
    if (j == 0) g[HID] = focal[b];
    __syncthreads();
    float acc = fc1b[j];
    for (int k = 0; k < HID + 1; k++) acc += g[k] * fc1w[(size_t)k * HID + j];
    float a = fmaxf(acc, 0.0f);
    red[j] = a * fc2w[j];
    __syncthreads();
    for (int s = 256; s > 0; s >>= 1) {
        if (j < s) red[j] += red[j + s];
        __syncthreads();
    }
    if (j == 0) out[b] = sigmoidf_(red[0] + fc2b[0]);
}

// ---------------- launch ----------------
extern "C" void kernel_launch(void* const* d_in, const int* in_sizes, int n_in,
                              void* d_out, int out_size) {
    const int*   x     = (const int*)  d_in[0];
    const int*   edge  = (const int*)  d_in[1];
    const float* focal = (const float*)d_in[3];
    const float* emb   = (const float*)d_in[4];
    const float* W1    = (const float*)d_in[5];
    const float* b1    = (const float*)d_in[6];
    const float* W2    = (const float*)d_in[7];
    const float* b2    = (const float*)d_in[8];
    const float* Wih   = (const float*)d_in[9];
    const float* Whh   = (const float*)d_in[10];
    const float* bih   = (const float*)d_in[11];
    const float* bhh   = (const float*)d_in[12];
    const float* fc1w  = (const float*)d_in[13];
    const float* fc1b  = (const float*)d_in[14];
    const float* fc2w  = (const float*)d_in[15];
    const float* fc2b  = (const float*)d_in[16];
    int E = in_sizes[1] / 2;
    const int* src = edge;
    const int* dst = edge + E;

    float *h0, *t, *h1, *h2, *gi, *gi2, *dinv, *hbuf, *hsum, *ccoef;
    int *deg, *off, *cursor, *csrc, *bar;
    cudaGetSymbolAddress((void**)&h0,    g_h0);
    cudaGetSymbolAddress((void**)&t,     g_t);
    cudaGetSymbolAddress((void**)&h1,    g_h1);
    cudaGetSymbolAddress((void**)&h2,    g_h2);
    cudaGetSymbolAddress((void**)&gi,    g_gi);
    cudaGetSymbolAddress((void**)&gi2,   g_gi2);
    cudaGetSymbolAddress((void**)&deg,   g_deg);
    cudaGetSymbolAddress((void**)&dinv,  g_dinv);
    cudaGetSymbolAddress((void**)&off,   g_off);
    cudaGetSymbolAddress((void**)&cursor,g_cursor);
    cudaGetSymbolAddress((void**)&csrc,  g_csrc);
    cudaGetSymbolAddress((void**)&ccoef, g_ccoef);
    cudaGetSymbolAddress((void**)&hbuf,  g_hbuf);
    cudaGetSymbolAddress((void**)&hsum,  g_hsum);
    cudaGetSymbolAddress((void**)&bar,   g_bar);

    cudaFuncSetAttribute(k_gru_all, cudaFuncAttributeMaxDynamicSharedMemorySize, GRU_SMEM);

    // CSR build (graph fixed for both layers)
    cudaMemsetAsync(deg, 0, N_NODES * sizeof(int), 0);
    k_count<<<(E + 255) / 256, 256>>>(dst, deg, E);
    k_dinv<<<N_NODES / 256, 256>>>(deg, dinv);
    k_scan<<<1, 1024>>>(deg, off, cursor);
    k_fill<<<(E + 255) / 256, 256>>>(src, dst, dinv, off, cursor, csrc, ccoef, E);

    // GCN layer 1
    k_embed<<<N_NODES, 256>>>(x, emb, h0);
    sgemm_kernel<false, false><<<dim3(HID / 64, N_NODES / 64), 256>>>(h0, W1, nullptr, t, N_NODES, HID, DIM);
    k_gather<<<N_NODES / 2, 256>>>(t, csrc, ccoef, off, dinv, b1, h1);

    // GCN layer 2
    sgemm_kernel<false, false><<<dim3(HID / 64, N_NODES / 64), 256>>>(h1, W2, nullptr, t, N_NODES, HID, HID);
    k_gather<<<N_NODES / 2, 256>>>(t, csrc, ccoef, off, dinv, b2, h2);

    // GRU input gates for all timesteps: gi = h2 @ Wih^T + bih, then transpose
    sgemm_kernel<true, true><<<dim3(GI3 / 64, N_NODES / 64), 256>>>(h2, Wih, bih, gi, N_NODES, GI3, HID);
    k_tr<<<dim3(LSEQ, GI3 / 128), 256>>>(gi, gi2);

    // persistent GRU
    cudaMemsetAsync(hbuf, 0, NB * HID * sizeof(float), 0);   // hbuf[0] = h_0 = 0
    cudaMemsetAsync(bar, 0, 4 * 32 * sizeof(int), 0);
    k_gru_all<<<128, 256, GRU_SMEM>>>(gi2, Whh, bhh, hsum, hbuf, hbuf + NB * HID, bar);

    // head
    k_head<<<NB, 512>>>(hsum, focal, fc1w, fc1b, fc2w, fc2b, (float*)d_out);
}